// round 1
// baseline (speedup 1.0000x reference)
#include <cuda_runtime.h>
#include <cstddef>

#define Bb 32
#define Dd 256
#define Ll 4096
#define Kk 1024
#define Nn (Bb*Ll)            // 131072 rows
#define NDL (Bb*Dd*Ll)        // 33554432 z_q elements

#define ROWS 64               // rows per argmin block
#define ZS 260                // padded smem row stride (floats)
#define ES 260
#define TL 32                 // l-tile for gather

__device__ int    g_idx[Nn];
__device__ float  g_enorm[Kk];
__device__ double g_acc;

// ---------------------------------------------------------------------------
// prep: per-code squared norms + zero loss accumulator
// ---------------------------------------------------------------------------
__global__ void vq_prep_kernel(const float* __restrict__ emb) {
    int k = blockIdx.x * blockDim.x + threadIdx.x;
    if (k == 0) g_acc = 0.0;
    if (k < Kk) {
        const float* row = emb + (size_t)k * Dd;
        float s = 0.f;
        #pragma unroll 8
        for (int d = 0; d < Dd; d++) { float v = row[d]; s += v * v; }
        g_enorm[k] = s;
    }
}

// ---------------------------------------------------------------------------
// argmin: fused distance + argmin. Block = 64 rows x all K.
//   dist = (||z||^2 + ||e||^2) - 2*(z.e)   computed in fp32 to mirror the
//   reference's quantization (||z||^2 ~ 256 -> ulp 3e-5 bins, ties -> low idx)
// ---------------------------------------------------------------------------
extern __shared__ float s_dyn[];

__global__ void __launch_bounds__(256)
vq_argmin_kernel(const float* __restrict__ z, const float* __restrict__ emb) {
    float* zs = s_dyn;               // [ROWS][ZS]
    float* es = s_dyn + ROWS * ZS;   // [64][ES]
    __shared__ float zn[ROWS];

    const int tid  = threadIdx.x;
    const int row0 = blockIdx.x * ROWS;
    const int b    = row0 >> 12;          // 4096 rows per batch
    const int l0   = row0 & (Ll - 1);
    const float* zb = z + (size_t)b * Dd * Ll + l0;

    // stage z tile: zs[lr][d] = z[b, d, l0+lr]; coalesced along lr
    for (int i = tid; i < ROWS * Dd; i += 256) {
        int d = i >> 6, lr = i & 63;
        zs[lr * ZS + d] = zb[(size_t)d * Ll + lr];
    }
    __syncthreads();

    // per-row ||z||^2 (sequential fp32 like the reference's fp32 reduce)
    if (tid < ROWS) {
        float s = 0.f;
        #pragma unroll 8
        for (int d = 0; d < Dd; d++) { float v = zs[tid * ZS + d]; s += v * v; }
        zn[tid] = s;
    }
    __syncthreads();

    const int tx = tid & 15;   // k dimension
    const int ty = tid >> 4;   // row dimension

    float bestv[4];
    int   besti[4];
    float znv[4];
    #pragma unroll
    for (int i = 0; i < 4; i++) {
        bestv[i] = 3.4e38f;
        besti[i] = 0;
        znv[i]   = zn[ty + 16 * i];
    }

    for (int kt = 0; kt < Kk; kt += 64) {
        __syncthreads();
        // stage e tile: es[kr][d] = emb[kt+kr, d]; coalesced along d
        for (int i = tid; i < 64 * Dd; i += 256) {
            int kr = i >> 8, d = i & 255;
            es[kr * ES + d] = emb[(size_t)(kt + kr) * Dd + d];
        }
        __syncthreads();

        float acc[4][4];
        #pragma unroll
        for (int i = 0; i < 4; i++)
            #pragma unroll
            for (int j = 0; j < 4; j++) acc[i][j] = 0.f;

        #pragma unroll 4
        for (int d4 = 0; d4 < Dd / 4; d4++) {
            float4 zv[4], ev[4];
            #pragma unroll
            for (int i = 0; i < 4; i++)
                zv[i] = *(const float4*)&zs[(ty + 16 * i) * ZS + 4 * d4];
            #pragma unroll
            for (int j = 0; j < 4; j++)
                ev[j] = *(const float4*)&es[(tx + 16 * j) * ES + 4 * d4];
            #pragma unroll
            for (int i = 0; i < 4; i++)
                #pragma unroll
                for (int j = 0; j < 4; j++) {
                    acc[i][j] = fmaf(zv[i].x, ev[j].x, acc[i][j]);
                    acc[i][j] = fmaf(zv[i].y, ev[j].y, acc[i][j]);
                    acc[i][j] = fmaf(zv[i].z, ev[j].z, acc[i][j]);
                    acc[i][j] = fmaf(zv[i].w, ev[j].w, acc[i][j]);
                }
        }

        // argmin update; in-thread k order is ascending -> strict < keeps lowest idx
        #pragma unroll
        for (int j = 0; j < 4; j++) {
            int k = kt + tx + 16 * j;
            float en = g_enorm[k];
            #pragma unroll
            for (int i = 0; i < 4; i++) {
                float dist = (znv[i] + en) - 2.0f * acc[i][j];
                if (dist < bestv[i]) { bestv[i] = dist; besti[i] = k; }
            }
        }
    }

    // reduce across 16 tx lanes (half-warp), tie -> lower index
    #pragma unroll
    for (int off = 8; off; off >>= 1) {
        #pragma unroll
        for (int i = 0; i < 4; i++) {
            float ov = __shfl_down_sync(0xffffffffu, bestv[i], off, 16);
            int   oi = __shfl_down_sync(0xffffffffu, besti[i], off, 16);
            if (ov < bestv[i] || (ov == bestv[i] && oi < besti[i])) {
                bestv[i] = ov; besti[i] = oi;
            }
        }
    }
    if (tx == 0) {
        #pragma unroll
        for (int i = 0; i < 4; i++)
            g_idx[row0 + ty + 16 * i] = besti[i];
    }
}

// ---------------------------------------------------------------------------
// gather: z_q_st = embedding[idx] scattered to (B,D,L); fused sum((z-q)^2)
// ---------------------------------------------------------------------------
__global__ void __launch_bounds__(256)
vq_gather_kernel(const float* __restrict__ z, const float* __restrict__ emb,
                 float* __restrict__ out) {
    __shared__ float q[TL][Dd + 1];   // stride 257 -> conflict-free transpose reads
    __shared__ int   idxs[TL];
    __shared__ float wsum[8];

    const int tid = threadIdx.x;
    const int t   = blockIdx.x;            // Nn/TL tiles
    const int b   = t >> 7;                // 128 tiles per batch (4096/32)
    const int l0  = (t & 127) * TL;
    const int rbase = b * Ll + l0;

    if (tid < TL) idxs[tid] = g_idx[rbase + tid];
    __syncthreads();

    // gather code rows: one full contiguous row per 256-thread pass
    for (int i = tid; i < TL * Dd; i += 256) {
        int r = i >> 8, d = i & 255;
        q[r][d] = emb[(size_t)idxs[r] * Dd + d];
    }
    __syncthreads();

    float lsum = 0.f;
    const float* zb = z   + (size_t)b * Dd * Ll + l0;
    float*       ob = (float*)out + (size_t)b * Dd * Ll + l0;
    for (int i = tid; i < Dd * TL; i += 256) {
        int d = i >> 5, lr = i & 31;       // 32 consecutive l -> coalesced
        float v  = q[lr][d];
        float ze = zb[(size_t)d * Ll + lr];
        ob[(size_t)d * Ll + lr] = v;
        float df = ze - v;
        lsum += df * df;
    }

    // block reduce -> one double atomic
    #pragma unroll
    for (int off = 16; off; off >>= 1)
        lsum += __shfl_xor_sync(0xffffffffu, lsum, off);
    if ((tid & 31) == 0) wsum[tid >> 5] = lsum;
    __syncthreads();
    if (tid == 0) {
        float s = 0.f;
        #pragma unroll
        for (int w = 0; w < 8; w++) s += wsum[w];
        atomicAdd(&g_acc, (double)s);
    }
}

// ---------------------------------------------------------------------------
// tail: indices region (cast to float)
// ---------------------------------------------------------------------------
__global__ void vq_tail_kernel(float* __restrict__ out) {
    int i = blockIdx.x * blockDim.x + threadIdx.x;
    if (i < Nn) out[NDL + i] = (float)g_idx[i];
}

// ---------------------------------------------------------------------------
// losses: vq = 1.25*mse, codebook = mse, beta*commit = 0.25*mse
// ---------------------------------------------------------------------------
__global__ void vq_loss_kernel(float* __restrict__ out) {
    double mse = g_acc / (double)NDL;
    out[NDL + Nn + 0] = (float)(1.25 * mse);
    out[NDL + Nn + 1] = (float)mse;
    out[NDL + Nn + 2] = (float)(0.25 * mse);
}

// ---------------------------------------------------------------------------
extern "C" void kernel_launch(void* const* d_in, const int* in_sizes, int n_in,
                              void* d_out, int out_size) {
    const float* z   = (const float*)d_in[0];
    const float* emb = (const float*)d_in[1];
    // robustness: identify inputs by size if order differs
    if (n_in >= 2 && in_sizes[0] == Kk * Dd && in_sizes[1] == NDL) {
        emb = (const float*)d_in[0];
        z   = (const float*)d_in[1];
    }
    float* out = (float*)d_out;

    const int smem_bytes = (ROWS * ZS + 64 * ES) * (int)sizeof(float);
    cudaFuncSetAttribute(vq_argmin_kernel,
                         cudaFuncAttributeMaxDynamicSharedMemorySize, smem_bytes);

    vq_prep_kernel<<<(Kk + 255) / 256, 256>>>(emb);
    vq_argmin_kernel<<<Nn / ROWS, 256, smem_bytes>>>(z, emb);
    vq_gather_kernel<<<Nn / TL, 256>>>(z, emb, out);
    if (out_size >= NDL + Nn)
        vq_tail_kernel<<<(Nn + 255) / 256, 256>>>(out);
    if (out_size >= NDL + Nn + 3)
        vq_loss_kernel<<<1, 1>>>(out);
}